// round 4
// baseline (speedup 1.0000x reference)
#include <cuda_runtime.h>
#include <cuda_bf16.h>
#include <cstdint>

// Problem dims
#define T_TOK 4096
#define D_DIM 1024
#define E_EXP 8
#define H_DIM 4096

// ---------------- device scratch (no allocations allowed) ----------------
__device__ int   g_expert[T_TOK];
__device__ int   g_counts[E_EXP];
__device__ int   g_offsets[E_EXP + 1];
__device__ int   g_cursor[E_EXP];
__device__ int   g_perm[T_TOK];
__device__ float g_probs[T_TOK * E_EXP];
__device__ float g_hidden[(size_t)T_TOK * H_DIM];   // 64 MB scratch for expert hidden

// ---------------- helpers ----------------
__device__ __forceinline__ uint32_t f2tf(float x) {
    uint32_t u;
    asm("cvt.rna.tf32.f32 %0, %1;" : "=r"(u) : "f"(x));
    return u;
}

__device__ __forceinline__ float4 cvt4_tf32(float4 v) {
    v.x = __uint_as_float(f2tf(v.x));
    v.y = __uint_as_float(f2tf(v.y));
    v.z = __uint_as_float(f2tf(v.z));
    v.w = __uint_as_float(f2tf(v.w));
    return v;
}

__device__ __forceinline__ void mma_tf32(float* c, const uint32_t* a, const uint32_t* b) {
    asm volatile(
        "mma.sync.aligned.m16n8k8.row.col.f32.tf32.tf32.f32 "
        "{%0,%1,%2,%3}, {%4,%5,%6,%7}, {%8,%9}, {%0,%1,%2,%3};"
        : "+f"(c[0]), "+f"(c[1]), "+f"(c[2]), "+f"(c[3])
        : "r"(a[0]), "r"(a[1]), "r"(a[2]), "r"(a[3]), "r"(b[0]), "r"(b[1]));
}

__device__ __forceinline__ float gelu_exact(float v) {
    return 0.5f * v * (1.0f + erff(v * 0.70710678118654752440f));
}

// ---------------- kernel 0: zero counters ----------------
__global__ void init_kernel() {
    if (threadIdx.x < E_EXP) g_counts[threadIdx.x] = 0;
}

// ---------------- kernel 1: router (one warp per token) ----------------
__global__ void router_kernel(const float* __restrict__ x,
                              const float* __restrict__ gum,
                              const float* __restrict__ rw,
                              const float* __restrict__ rb) {
    int gwarp = (blockIdx.x * blockDim.x + threadIdx.x) >> 5;
    int lane  = threadIdx.x & 31;
    if (gwarp >= T_TOK) return;

    const float* xr = x + (size_t)gwarp * D_DIM;
    float acc[8] = {0.f, 0.f, 0.f, 0.f, 0.f, 0.f, 0.f, 0.f};

    for (int d = lane; d < D_DIM; d += 32) {
        float xv = xr[d];
        float4 wa = *reinterpret_cast<const float4*>(rw + (size_t)d * 8);
        float4 wb = *reinterpret_cast<const float4*>(rw + (size_t)d * 8 + 4);
        acc[0] += xv * wa.x; acc[1] += xv * wa.y;
        acc[2] += xv * wa.z; acc[3] += xv * wa.w;
        acc[4] += xv * wb.x; acc[5] += xv * wb.y;
        acc[6] += xv * wb.z; acc[7] += xv * wb.w;
    }
    #pragma unroll
    for (int o = 16; o > 0; o >>= 1) {
        #pragma unroll
        for (int e = 0; e < 8; e++)
            acc[e] += __shfl_xor_sync(0xffffffffu, acc[e], o);
    }

    if (lane == 0) {
        float lg[8];
        #pragma unroll
        for (int e = 0; e < 8; e++) lg[e] = acc[e] + rb[e];

        // argmax of logits + gumbel (first index wins on tie, like jnp.argmax)
        float zmax = -1e30f; int eid = 0; float lmax = -1e30f;
        #pragma unroll
        for (int e = 0; e < 8; e++) {
            float z = lg[e] + gum[(size_t)gwarp * 8 + e];
            if (z > zmax) { zmax = z; eid = e; }
            if (lg[e] > lmax) lmax = lg[e];
        }
        // softmax(logits) for aux loss
        float p[8], s = 0.f;
        #pragma unroll
        for (int e = 0; e < 8; e++) { p[e] = expf(lg[e] - lmax); s += p[e]; }
        float inv = 1.0f / s;
        #pragma unroll
        for (int e = 0; e < 8; e++) g_probs[(size_t)gwarp * 8 + e] = p[e] * inv;

        g_expert[gwarp] = eid;
        atomicAdd(&g_counts[eid], 1);
    }
}

// ---------------- kernel 2: offsets scan + aux loss (deterministic) ----------------
__global__ void scan_aux_kernel(float* __restrict__ out, int out_size) {
    int tid  = threadIdx.x;
    int warp = tid >> 5;
    int lane = tid & 31;
    __shared__ float s_imp[8];

    // warp e reduces column e of g_probs in a fixed order (bit-deterministic)
    float s = 0.f;
    for (int t = lane; t < T_TOK; t += 32) s += g_probs[(size_t)t * 8 + warp];
    #pragma unroll
    for (int o = 16; o > 0; o >>= 1) s += __shfl_xor_sync(0xffffffffu, s, o);
    if (lane == 0) s_imp[warp] = s;
    __syncthreads();

    if (tid == 0) {
        int off = 0;
        #pragma unroll
        for (int e = 0; e < E_EXP; e++) {
            g_offsets[e] = off;
            g_cursor[e]  = off;
            off += g_counts[e];
        }
        g_offsets[E_EXP] = off;

        float aux = 0.f;
        #pragma unroll
        for (int e = 0; e < E_EXP; e++) {
            float d = s_imp[e] * (1.0f / (float)T_TOK) - (1.0f / (float)E_EXP);
            aux += d * d;
        }
        aux *= (1.0f / (float)E_EXP);
        if (out_size > T_TOK * D_DIM) out[(size_t)T_TOK * D_DIM] = aux;
    }
}

// ---------------- kernel 3: build permutation (group tokens by expert) ----------------
__global__ void perm_kernel() {
    int t = blockIdx.x * blockDim.x + threadIdx.x;
    if (t < T_TOK) {
        int e = g_expert[t];
        int slot = atomicAdd(&g_cursor[e], 1);
        g_perm[slot] = t;
    }
}

// ---------------- kernels 4/5: grouped tf32 GEMM (128x128 tile, KC=16) ----------------
// PHASE 1: hidden[slot] = gelu(x[perm[slot]] @ w1[e] + b1[e])   K=1024, N=4096
// PHASE 2: out[perm[slot]] = hidden[slot] @ w2[e] + b2[e]       K=4096, N=1024
template <int PHASE>
__global__ __launch_bounds__(256, 2)
void ffn_gemm(const float* __restrict__ Aglob, const float* __restrict__ W,
              const float* __restrict__ bias, float* __restrict__ out) {
    constexpr int KTOT = (PHASE == 1) ? D_DIM : H_DIM;
    constexpr int NTOT = (PHASE == 1) ? H_DIM : D_DIM;
    constexpr int KIT  = KTOT / 16;

    int nt = blockIdx.x;
    int ms = blockIdx.y;
    int e  = ms >> 5;
    int mt = ms & 31;

    int cnt   = g_counts[e];
    int mbase = mt * 128;
    if (mbase >= cnt) return;
    int off        = g_offsets[e];
    int rows_valid = min(128, cnt - mbase);

    __shared__ float As[2][128][20];    // [m][k], pad 20 -> conflict-free A frags
    __shared__ float Bs[2][16][136];    // [k][n], pad 136 -> conflict-free B frags
    __shared__ int   rowtok[128];

    int tid = threadIdx.x;
    if (tid < 128)
        rowtok[tid] = (tid < rows_valid) ? g_perm[off + mbase + tid] : -1;
    __syncthreads();

    // staging chunk assignment: 512 float4 per operand per stage, 2 per thread
    const float* aptr[2]; bool av[2]; int rA[2], kA[2];
    const float* bptr[2]; int kB[2], nB[2];
    #pragma unroll
    for (int j = 0; j < 2; j++) {
        int c = tid + j * 256;
        rA[j] = c >> 2;
        kA[j] = (c & 3) << 2;
        if (PHASE == 1) {
            int tk = rowtok[rA[j]];
            av[j]  = (tk >= 0);
            aptr[j] = Aglob + (size_t)(av[j] ? tk : 0) * KTOT + kA[j];
        } else {
            av[j]  = (rA[j] < rows_valid);
            aptr[j] = g_hidden + (size_t)(off + mbase + (av[j] ? rA[j] : 0)) * KTOT + kA[j];
        }
        kB[j] = c >> 5;
        nB[j] = (c & 31) << 2;
        bptr[j] = W + (size_t)e * KTOT * NTOT + (size_t)kB[j] * NTOT + nt * 128 + nB[j];
    }

    int lane = tid & 31, warpId = tid >> 5;
    int g  = lane >> 2, tg = lane & 3;
    int wm = warpId & 1, wn = warpId >> 1;   // warp tile: 64 (m) x 32 (n)

    float acc[4][4][4];
    #pragma unroll
    for (int mi = 0; mi < 4; mi++)
        #pragma unroll
        for (int ni = 0; ni < 4; ni++)
            #pragma unroll
            for (int q = 0; q < 4; q++) acc[mi][ni][q] = 0.f;

    const float4 fz = make_float4(0.f, 0.f, 0.f, 0.f);

    // prologue: stage 0
    {
        float4 va[2], vb[2];
        #pragma unroll
        for (int j = 0; j < 2; j++) {
            va[j] = av[j] ? *reinterpret_cast<const float4*>(aptr[j]) : fz;
            vb[j] = *reinterpret_cast<const float4*>(bptr[j]);
        }
        #pragma unroll
        for (int j = 0; j < 2; j++) {
            *reinterpret_cast<float4*>(&As[0][rA[j]][kA[j]]) = cvt4_tf32(va[j]);
            *reinterpret_cast<float4*>(&Bs[0][kB[j]][nB[j]]) = cvt4_tf32(vb[j]);
        }
    }
    __syncthreads();

    int buf = 0;
    for (int kb = 0; kb < KIT; kb++) {
        float4 va[2], vb[2];
        bool pre = (kb + 1 < KIT);
        if (pre) {
            int k0 = (kb + 1) * 16;
            #pragma unroll
            for (int j = 0; j < 2; j++) {
                va[j] = av[j] ? *reinterpret_cast<const float4*>(aptr[j] + k0) : fz;
                vb[j] = *reinterpret_cast<const float4*>(bptr[j] + (size_t)k0 * NTOT);
            }
        }

        const float(*Asb)[20]  = As[buf];
        const float(*Bsb)[136] = Bs[buf];
        #pragma unroll
        for (int ks = 0; ks < 2; ks++) {
            int k8 = ks * 8;
            uint32_t af[4][4], bf[4][2];
            #pragma unroll
            for (int mi = 0; mi < 4; mi++) {
                int m0 = wm * 64 + mi * 16 + g;
                af[mi][0] = __float_as_uint(Asb[m0    ][k8 + tg    ]);
                af[mi][1] = __float_as_uint(Asb[m0 + 8][k8 + tg    ]);
                af[mi][2] = __float_as_uint(Asb[m0    ][k8 + tg + 4]);
                af[mi][3] = __float_as_uint(Asb[m0 + 8][k8 + tg + 4]);
            }
            #pragma unroll
            for (int ni = 0; ni < 4; ni++) {
                int n0 = wn * 32 + ni * 8 + g;
                bf[ni][0] = __float_as_uint(Bsb[k8 + tg    ][n0]);
                bf[ni][1] = __float_as_uint(Bsb[k8 + tg + 4][n0]);
            }
            #pragma unroll
            for (int mi = 0; mi < 4; mi++)
                #pragma unroll
                for (int ni = 0; ni < 4; ni++)
                    mma_tf32(acc[mi][ni], af[mi], bf[ni]);
        }

        if (pre) {
            int nb = buf ^ 1;
            #pragma unroll
            for (int j = 0; j < 2; j++) {
                *reinterpret_cast<float4*>(&As[nb][rA[j]][kA[j]]) = cvt4_tf32(va[j]);
                *reinterpret_cast<float4*>(&Bs[nb][kB[j]][nB[j]]) = cvt4_tf32(vb[j]);
            }
        }
        __syncthreads();
        buf ^= 1;
    }

    // epilogue
    #pragma unroll
    for (int mi = 0; mi < 4; mi++) {
        #pragma unroll
        for (int half = 0; half < 2; half++) {
            int r = wm * 64 + mi * 16 + g + half * 8;
            if (r >= rows_valid) continue;
            size_t orow;
            if (PHASE == 1) {
                orow = (size_t)(off + mbase + r) * H_DIM + (size_t)nt * 128;
            } else {
                int tok = rowtok[r];
                orow = (size_t)tok * D_DIM + (size_t)nt * 128;
            }
            #pragma unroll
            for (int ni = 0; ni < 4; ni++) {
                int cl = wn * 32 + ni * 8 + tg * 2;
                float bv0 = bias[(size_t)e * NTOT + nt * 128 + cl];
                float bv1 = bias[(size_t)e * NTOT + nt * 128 + cl + 1];
                float v0 = acc[mi][ni][half * 2 + 0] + bv0;
                float v1 = acc[mi][ni][half * 2 + 1] + bv1;
                if (PHASE == 1) {
                    g_hidden[orow + cl]     = gelu_exact(v0);
                    g_hidden[orow + cl + 1] = gelu_exact(v1);
                } else {
                    out[orow + cl]     = v0;
                    out[orow + cl + 1] = v1;
                }
            }
        }
    }
}

// ---------------- host entry ----------------
extern "C" void kernel_launch(void* const* d_in, const int* in_sizes, int n_in,
                              void* d_out, int out_size) {
    const float* x   = (const float*)d_in[0];   // (4,1024,1024)
    const float* gum = (const float*)d_in[1];   // (4096,8)
    const float* rw  = (const float*)d_in[2];   // (1024,8)
    const float* rb  = (const float*)d_in[3];   // (8,)
    const float* w1  = (const float*)d_in[4];   // (8,1024,4096)
    const float* b1  = (const float*)d_in[5];   // (8,4096)
    const float* w2  = (const float*)d_in[6];   // (8,4096,1024)
    const float* b2  = (const float*)d_in[7];   // (8,1024)
    float* out = (float*)d_out;

    // best-effort occupancy hints (host-side only; no-ops on replay)
    cudaFuncSetAttribute((const void*)ffn_gemm<1>,
                         cudaFuncAttributePreferredSharedMemoryCarveout, 100);
    cudaFuncSetAttribute((const void*)ffn_gemm<2>,
                         cudaFuncAttributePreferredSharedMemoryCarveout, 100);

    init_kernel<<<1, 32>>>();
    router_kernel<<<512, 256>>>(x, gum, rw, rb);
    scan_aux_kernel<<<1, 256>>>(out, out_size);
    perm_kernel<<<16, 256>>>();
    // GEMM1: N=4096 -> 32 n-tiles; 8 experts x up-to-32 m-tiles
    ffn_gemm<1><<<dim3(32, 256), 256>>>(x, w1, b1, out);
    // GEMM2: N=1024 -> 8 n-tiles
    ffn_gemm<2><<<dim3(8, 256), 256>>>(x, w2, b2, out);
}

// round 10
// speedup vs baseline: 1.2026x; 1.2026x over previous
#include <cuda_runtime.h>
#include <cuda_bf16.h>
#include <cstdint>

// Problem dims
#define T_TOK 4096
#define D_DIM 1024
#define E_EXP 8
#define H_DIM 4096

// ---------------- device scratch (no allocations allowed) ----------------
__device__ int   g_expert[T_TOK];
__device__ int   g_counts[E_EXP];
__device__ int   g_offsets[E_EXP + 1];
__device__ int   g_cursor[E_EXP];
__device__ int   g_perm[T_TOK];
__device__ float g_probs[T_TOK * E_EXP];
__device__ float g_hidden[(size_t)T_TOK * H_DIM];   // 64 MB scratch

// ---------------- helpers ----------------
__device__ __forceinline__ uint32_t f2tf(float x) {
    uint32_t u; asm("cvt.rna.tf32.f32 %0, %1;" : "=r"(u) : "f"(x)); return u;
}
__device__ __forceinline__ float4 cvt4_tf32(float4 v) {
    v.x = __uint_as_float(f2tf(v.x)); v.y = __uint_as_float(f2tf(v.y));
    v.z = __uint_as_float(f2tf(v.z)); v.w = __uint_as_float(f2tf(v.w));
    return v;
}
__device__ __forceinline__ float gelu_exact(float v) {
    return 0.5f * v * (1.0f + erff(v * 0.70710678118654752440f));
}
__device__ __forceinline__ uint32_t smem_u32(const void* p) {
    uint32_t a;
    asm("{ .reg .u64 t; cvta.to.shared.u64 t, %1; cvt.u32.u64 %0, t; }" : "=r"(a) : "l"(p));
    return a;
}
__device__ __forceinline__ void mma_tf32(float* c, const uint32_t* a, const uint32_t* b) {
    asm volatile(
        "mma.sync.aligned.m16n8k8.row.col.f32.tf32.tf32.f32 "
        "{%0,%1,%2,%3}, {%4,%5,%6,%7}, {%8,%9}, {%0,%1,%2,%3};"
        : "+f"(c[0]), "+f"(c[1]), "+f"(c[2]), "+f"(c[3])
        : "r"(a[0]), "r"(a[1]), "r"(a[2]), "r"(a[3]), "r"(b[0]), "r"(b[1]));
}
__device__ __forceinline__ void cp_async16(uint32_t saddr, const void* gptr) {
    asm volatile("cp.async.cg.shared.global [%0], [%1], 16;" :: "r"(saddr), "l"(gptr));
}
__device__ __forceinline__ void cp_commit() {
    asm volatile("cp.async.commit_group;" ::: "memory");
}
template <int N>
__device__ __forceinline__ void cp_wait() {
    asm volatile("cp.async.wait_group %0;" :: "n"(N) : "memory");
}

// ---------------- kernel 0: zero counters ----------------
__global__ void init_kernel() {
    if (threadIdx.x < E_EXP) g_counts[threadIdx.x] = 0;
}

// ---------------- kernel 1: router (one warp per token) ----------------
__global__ void router_kernel(const float* __restrict__ x,
                              const float* __restrict__ gum,
                              const float* __restrict__ rw,
                              const float* __restrict__ rb) {
    int gwarp = (blockIdx.x * blockDim.x + threadIdx.x) >> 5;
    int lane  = threadIdx.x & 31;
    if (gwarp >= T_TOK) return;

    const float* xr = x + (size_t)gwarp * D_DIM;
    float acc[8] = {0.f,0.f,0.f,0.f,0.f,0.f,0.f,0.f};
    for (int d = lane; d < D_DIM; d += 32) {
        float xv = xr[d];
        float4 wa = *reinterpret_cast<const float4*>(rw + (size_t)d * 8);
        float4 wb = *reinterpret_cast<const float4*>(rw + (size_t)d * 8 + 4);
        acc[0] += xv * wa.x; acc[1] += xv * wa.y; acc[2] += xv * wa.z; acc[3] += xv * wa.w;
        acc[4] += xv * wb.x; acc[5] += xv * wb.y; acc[6] += xv * wb.z; acc[7] += xv * wb.w;
    }
    #pragma unroll
    for (int o = 16; o > 0; o >>= 1)
        #pragma unroll
        for (int e = 0; e < 8; e++)
            acc[e] += __shfl_xor_sync(0xffffffffu, acc[e], o);

    if (lane == 0) {
        float lg[8];
        #pragma unroll
        for (int e = 0; e < 8; e++) lg[e] = acc[e] + rb[e];
        float zmax = -1e30f; int eid = 0; float lmax = -1e30f;
        #pragma unroll
        for (int e = 0; e < 8; e++) {
            float z = lg[e] + gum[(size_t)gwarp * 8 + e];
            if (z > zmax) { zmax = z; eid = e; }
            if (lg[e] > lmax) lmax = lg[e];
        }
        float p[8], s = 0.f;
        #pragma unroll
        for (int e = 0; e < 8; e++) { p[e] = expf(lg[e] - lmax); s += p[e]; }
        float inv = 1.0f / s;
        #pragma unroll
        for (int e = 0; e < 8; e++) g_probs[(size_t)gwarp * 8 + e] = p[e] * inv;
        g_expert[gwarp] = eid;
        atomicAdd(&g_counts[eid], 1);
    }
}

// ---------------- kernel 2: offsets scan + aux loss (deterministic) ----------------
__global__ void scan_aux_kernel(float* __restrict__ out, int out_size) {
    int tid  = threadIdx.x, warp = tid >> 5, lane = tid & 31;
    __shared__ float s_imp[8];
    float s = 0.f;
    for (int t = lane; t < T_TOK; t += 32) s += g_probs[(size_t)t * 8 + warp];
    #pragma unroll
    for (int o = 16; o > 0; o >>= 1) s += __shfl_xor_sync(0xffffffffu, s, o);
    if (lane == 0) s_imp[warp] = s;
    __syncthreads();
    if (tid == 0) {
        int off = 0;
        #pragma unroll
        for (int e = 0; e < E_EXP; e++) { g_offsets[e] = off; g_cursor[e] = off; off += g_counts[e]; }
        g_offsets[E_EXP] = off;
        float aux = 0.f;
        #pragma unroll
        for (int e = 0; e < E_EXP; e++) {
            float d = s_imp[e] * (1.0f / (float)T_TOK) - (1.0f / (float)E_EXP);
            aux += d * d;
        }
        aux *= (1.0f / (float)E_EXP);
        if (out_size > T_TOK * D_DIM) out[(size_t)T_TOK * D_DIM] = aux;
    }
}

// ---------------- kernel 3: build permutation ----------------
__global__ void perm_kernel() {
    int t = blockIdx.x * blockDim.x + threadIdx.x;
    if (t < T_TOK) {
        int e = g_expert[t];
        int slot = atomicAdd(&g_cursor[e], 1);
        g_perm[slot] = t;
    }
}

// ---------------- grouped tf32 GEMM, cp.async 3-stage pipeline ----------------
// PHASE 1: hidden[slot] = round_tf32(gelu(x[perm[slot]] @ w1[e] + b1[e]))  K=1024, N=4096
// PHASE 2: out[perm[slot]] = hidden[slot] @ w2[e] + b2[e]                  K=4096, N=1024
// NOTE: g_hidden is referenced ONLY from device code (a __device__ symbol
// passed from host as a kernel arg is the host shadow — that was the R5 bug).
template <int PHASE>
__global__ __launch_bounds__(256, 2)
void moe_gemm(const float* __restrict__ Aglob, const float* __restrict__ W,
              const float* __restrict__ bias, float* __restrict__ out) {
    constexpr int KTOT = (PHASE == 1) ? D_DIM : H_DIM;
    constexpr int NTOT = (PHASE == 1) ? H_DIM : D_DIM;
    constexpr int KC   = 32;
    constexpr int NKB  = KTOT / KC;
    constexpr int AROW = 36;                    // words per A row (pad 32->36)
    constexpr int BROW = 136;                   // words per B row (pad 128->136)
    constexpr int ABYTES = 128 * AROW * 4;      // 18432
    constexpr int BBYTES = KC * BROW * 4;       // 17408
    constexpr int STAGE  = ABYTES + BBYTES;     // 35840

    int nt = blockIdx.x, ms = blockIdx.y;
    int e  = ms >> 5, mt = ms & 31;
    int cnt = g_counts[e];
    int mbase = mt * 128;
    if (mbase >= cnt) return;
    int off = g_offsets[e];
    int rv  = min(128, cnt - mbase);

    extern __shared__ char smraw[];
    char* sm = (char*)(((uintptr_t)smraw + 127) & ~(uintptr_t)127);
    int*  rowtok = (int*)sm;
    char* stg    = sm + 1024;
    uint32_t stg_u = smem_u32(stg);

    int tid = threadIdx.x, lane = tid & 31, wid = tid >> 5;
    if (tid < 128) rowtok[tid] = g_perm[off + mbase + min(tid, rv - 1)];
    __syncthreads();

    // ---- staging maps (4 x 16B per thread for A and for B per chunk) ----
    int arow_ = tid >> 3, akq = tid & 7;       // A: row m=32j+arow_, quad akq
    const float* aG[4]; uint32_t aOFF[4];
    const float* bG[4]; uint32_t bOFF[4];
    #pragma unroll
    for (int j = 0; j < 4; j++) {
        int m = 32 * j + arow_;
        if (PHASE == 1)
            aG[j] = Aglob + (size_t)rowtok[m] * KTOT + akq * 4;
        else
            aG[j] = g_hidden + (size_t)(off + mbase + min(m, rv - 1)) * KTOT + akq * 4;
        aOFF[j] = (uint32_t)(m * (AROW * 4) + akq * 16);
        int k = 8 * j + wid;                   // B: row k=8j+wid, quad lane
        bG[j] = W + (size_t)e * KTOT * NTOT + (size_t)k * NTOT
                  + (size_t)nt * 128 + lane * 4;
        bOFF[j] = (uint32_t)(ABYTES + k * (BROW * 4) + lane * 16);
    }

    auto stage_chunk = [&](int c, int s) {
        uint32_t sb = (uint32_t)(s * STAGE);
        int k0 = c * KC;
        if (PHASE == 1) {
            #pragma unroll
            for (int j = 0; j < 4; j++) {
                float4 v = *reinterpret_cast<const float4*>(aG[j] + k0);
                v = cvt4_tf32(v);
                *reinterpret_cast<float4*>(stg + s * STAGE + aOFF[j]) = v;
            }
        } else {
            #pragma unroll
            for (int j = 0; j < 4; j++)
                cp_async16(stg_u + sb + aOFF[j], aG[j] + k0);
        }
        #pragma unroll
        for (int j = 0; j < 4; j++)
            cp_async16(stg_u + sb + bOFF[j], bG[j] + (size_t)k0 * NTOT);
        cp_commit();
    };

    int g  = lane >> 2, tg = lane & 3;
    int wm = wid & 1,  wn = wid >> 1;          // warp tile 64(m) x 32(n)

    float acc[4][4][4] = {};

    stage_chunk(0, 0);
    stage_chunk(1, 1);

    for (int c = 0; c < NKB; c++) {
        cp_wait<1>();
        __syncthreads();
        int s = c % 3;
        const float* Asb = (const float*)(stg + s * STAGE);
        const float* Bsb = (const float*)(stg + s * STAGE + ABYTES);
        #pragma unroll
        for (int ks = 0; ks < 4; ks++) {
            int k8 = ks * 8;
            uint32_t af[4][4], bf[4][2];
            #pragma unroll
            for (int mi = 0; mi < 4; mi++) {
                int r0 = wm * 64 + mi * 16 + g;
                af[mi][0] = __float_as_uint(Asb[(r0    ) * AROW + k8 + tg    ]);
                af[mi][1] = __float_as_uint(Asb[(r0 + 8) * AROW + k8 + tg    ]);
                af[mi][2] = __float_as_uint(Asb[(r0    ) * AROW + k8 + tg + 4]);
                af[mi][3] = __float_as_uint(Asb[(r0 + 8) * AROW + k8 + tg + 4]);
            }
            #pragma unroll
            for (int ni = 0; ni < 4; ni++) {
                int n0 = wn * 32 + ni * 8 + g;
                bf[ni][0] = __float_as_uint(Bsb[(k8 + tg    ) * BROW + n0]);
                bf[ni][1] = __float_as_uint(Bsb[(k8 + tg + 4) * BROW + n0]);
            }
            #pragma unroll
            for (int mi = 0; mi < 4; mi++)
                #pragma unroll
                for (int ni = 0; ni < 4; ni++)
                    mma_tf32(acc[mi][ni], af[mi], bf[ni]);
        }
        if (c + 2 < NKB) stage_chunk(c + 2, (c + 2) % 3);
        else             cp_commit();          // keep group count aligned
    }

    // ---- epilogue ----
    #pragma unroll
    for (int mi = 0; mi < 4; mi++) {
        #pragma unroll
        for (int h = 0; h < 2; h++) {
            int r = wm * 64 + mi * 16 + g + h * 8;
            if (r >= rv) continue;
            size_t orow = (PHASE == 1)
                ? (size_t)(off + mbase + r) * H_DIM + (size_t)nt * 128
                : (size_t)rowtok[r] * D_DIM + (size_t)nt * 128;
            #pragma unroll
            for (int ni = 0; ni < 4; ni++) {
                int cl = wn * 32 + ni * 8 + tg * 2;
                float b0 = bias[(size_t)e * NTOT + nt * 128 + cl];
                float b1 = bias[(size_t)e * NTOT + nt * 128 + cl + 1];
                float v0 = acc[mi][ni][h * 2 + 0] + b0;
                float v1 = acc[mi][ni][h * 2 + 1] + b1;
                if (PHASE == 1) {
                    // pre-round hidden to tf32 so GEMM2's A needs no cvt
                    g_hidden[orow + cl]     = __uint_as_float(f2tf(gelu_exact(v0)));
                    g_hidden[orow + cl + 1] = __uint_as_float(f2tf(gelu_exact(v1)));
                } else {
                    out[orow + cl]     = v0;
                    out[orow + cl + 1] = v1;
                }
            }
        }
    }
}

// ---------------- host entry ----------------
extern "C" void kernel_launch(void* const* d_in, const int* in_sizes, int n_in,
                              void* d_out, int out_size) {
    const float* x   = (const float*)d_in[0];   // (4,1024,1024)
    const float* gum = (const float*)d_in[1];   // (4096,8)
    const float* rw  = (const float*)d_in[2];   // (1024,8)
    const float* rb  = (const float*)d_in[3];   // (8,)
    const float* w1  = (const float*)d_in[4];   // (8,1024,4096)
    const float* b1  = (const float*)d_in[5];   // (8,4096)
    const float* w2  = (const float*)d_in[6];   // (8,4096,1024)
    const float* b2  = (const float*)d_in[7];   // (8,1024)
    float* out = (float*)d_out;

    constexpr int SMEM_TOTAL = 1024 + 1024 + 3 * 35840;   // 109568 B
    cudaFuncSetAttribute((const void*)moe_gemm<1>,
                         cudaFuncAttributeMaxDynamicSharedMemorySize, SMEM_TOTAL);
    cudaFuncSetAttribute((const void*)moe_gemm<2>,
                         cudaFuncAttributeMaxDynamicSharedMemorySize, SMEM_TOTAL);

    init_kernel<<<1, 32>>>();
    router_kernel<<<512, 256>>>(x, gum, rw, rb);
    scan_aux_kernel<<<1, 256>>>(out, out_size);
    perm_kernel<<<16, 256>>>();
    // GEMM1: N=4096 -> 32 n-tiles of 128; y = expert*32 + m-slot
    moe_gemm<1><<<dim3(32, 256), 256, SMEM_TOTAL>>>(x, w1, b1, out);
    // GEMM2: N=1024 -> 8 n-tiles of 128 (A comes from g_hidden inside the kernel)
    moe_gemm<2><<<dim3(8, 256), 256, SMEM_TOTAL>>>(x, w2, b2, out);
}